// round 7
// baseline (speedup 1.0000x reference)
#include <cuda_runtime.h>
#include <cstdint>

// Per-batch class-presence bitmasks (bits 0..5), B=64. Written by presence
// kernel, read by loss kernel AFTER cudaGridDependencySynchronize() (PDL).
__device__ unsigned g_masks[64];

// ---------------------------------------------------------------------------
// Presence kernel: grid = B blocks x 32 threads (one warp, no smem, no BAR).
// ORs labels (0..5) into a 6-bit mask. First pass covers 128 labels:
// p(miss) ~ 6*(5/6)^128 ~ 4e-10 on uniform data; presence-OR is monotone so
// early exit is exact, adversarial data degrades to a full (correct) scan.
// Triggers programmatic launch completion after publishing its mask.
// ---------------------------------------------------------------------------
__global__ void __launch_bounds__(32, 32)
presence_kernel(const int* __restrict__ target, int n_vec4_per_batch) {
    const int lane = threadIdx.x;
    const int4* __restrict__ t4 = reinterpret_cast<const int4*>(target)
                                  + (long long)blockIdx.x * n_vec4_per_batch;

    unsigned acc = 0u;
    if (lane < n_vec4_per_batch) {
        int4 v = t4[lane];
        acc = (1u << (v.x & 31)) | (1u << (v.y & 31)) |
              (1u << (v.z & 31)) | (1u << (v.w & 31));
    }
    acc = __reduce_or_sync(0xffffffffu, acc) & 0x3Fu;

    if (acc != 0x3Fu) {                        // cold path: finish the scan
        for (int base = 32; base < n_vec4_per_batch; base += 32) {
            int idx = base + lane;
            unsigned a = 0u;
            if (idx < n_vec4_per_batch) {
                int4 v = t4[idx];
                a = (1u << (v.x & 31)) | (1u << (v.y & 31)) |
                    (1u << (v.z & 31)) | (1u << (v.w & 31));
            }
            acc |= __reduce_or_sync(0xffffffffu, a) & 0x3Fu;
            if (acc == 0x3Fu) break;
        }
    }

    if (lane == 0) g_masks[blockIdx.x] = acc;
    __threadfence();                            // mask visible before trigger
    cudaTriggerProgrammaticLaunchCompletion();
}

// ---------------------------------------------------------------------------
// Loss kernel (PDL secondary): 1 block x 384 threads, one (batch,class) term
// each. Prelude (se_pred load + clamped logs) runs CONCURRENTLY with the
// presence kernel; only select+reduce+store follow the dependency sync.
// ---------------------------------------------------------------------------
__global__ void __launch_bounds__(384, 1)
loss_kernel(const float* __restrict__ se_pred,
            float* __restrict__ out, int n_terms) {
    const int i = threadIdx.x;           // 0..383
    float v_present = 0.0f, v_absent = 0.0f;
    int b = 0, c = 0;
    if (i < n_terms) {
        b = i / 6;
        c = i - b * 6;
        const float p = se_pred[i];
        v_present = -fmaxf(logf(p),    -100.0f);   // t = 1 branch
        v_absent  = -fmaxf(log1pf(-p), -100.0f);   // t = 0 branch
    }

    cudaGridDependencySynchronize();     // wait for presence grid's writes

    float v = 0.0f;
    if (i < n_terms) {
        const unsigned m = __ldcg(&g_masks[b]);    // L2 read (cross-kernel)
        v = ((m >> c) & 1u) ? v_present : v_absent;
    }

    // Block reduction: 12 warps -> shared -> warp 0.
    __shared__ float sh[12];
    #pragma unroll
    for (int o = 16; o > 0; o >>= 1) v += __shfl_down_sync(0xffffffffu, v, o);
    if ((i & 31) == 0) sh[i >> 5] = v;
    __syncthreads();
    if (i < 32) {
        float s = (i < 12) ? sh[i] : 0.0f;
        #pragma unroll
        for (int o = 8; o > 0; o >>= 1) s += __shfl_down_sync(0xffffffffu, s, o);
        if (i == 0) out[0] = s / (float)n_terms;
    }
}

// ---------------------------------------------------------------------------
extern "C" void kernel_launch(void* const* d_in, const int* in_sizes, int n_in,
                              void* d_out, int out_size) {
    // Resolve inputs by size: se_pred has 64*6 = 384 elements; target is huge.
    int se_idx = 0, tg_idx = 1;
    if (n_in >= 2 && in_sizes[0] > in_sizes[1]) { se_idx = 1; tg_idx = 0; }

    const float* se_pred = (const float*)d_in[se_idx];
    const int*   target  = (const int*)d_in[tg_idx];
    float* out = (float*)d_out;

    const int n_terms   = in_sizes[se_idx];        // 384
    const int B         = n_terms / 6;             // 64
    const int per_batch = in_sizes[tg_idx] / B;    // 262144 int32 labels
    const int n_vec4    = per_batch / 4;           // int4 count per batch

    presence_kernel<<<B, 32>>>(target, n_vec4);

    // Secondary launch with programmatic stream serialization (PDL): it may
    // begin while presence_kernel runs; cudaGridDependencySynchronize() inside
    // provides the ordering.
    cudaLaunchAttribute attr;
    attr.id = cudaLaunchAttributeProgrammaticStreamSerialization;
    attr.val.programmaticStreamSerializationAllowed = 1;

    cudaLaunchConfig_t cfg = {};
    cfg.gridDim  = dim3(1, 1, 1);
    cfg.blockDim = dim3(384, 1, 1);
    cfg.dynamicSmemBytes = 0;
    cfg.stream = 0;
    cfg.attrs = &attr;
    cfg.numAttrs = 1;

    cudaLaunchKernelEx(&cfg, loss_kernel, se_pred, out, n_terms);
}

// round 8
// speedup vs baseline: 1.0795x; 1.0795x over previous
#include <cuda_runtime.h>
#include <cstdint>

// Per-batch class-presence bitmasks (bits 0..5), B=64. Written by presence
// kernel, read by loss kernel AFTER cudaGridDependencySynchronize() (PDL).
__device__ unsigned g_masks[64];

// ---------------------------------------------------------------------------
// Presence kernel: grid = B blocks x 32 threads (one warp, no smem, no BAR).
// ORs labels (0..5) into a 6-bit mask. First pass covers 128 labels:
// p(miss) ~ 6*(5/6)^128 ~ 4e-10 on uniform data; presence-OR is monotone so
// early exit is exact, adversarial data degrades to a full (correct) scan.
// Triggers programmatic launch completion after publishing its mask.
// ---------------------------------------------------------------------------
__global__ void __launch_bounds__(32, 32)
presence_kernel(const int* __restrict__ target, int n_vec4_per_batch) {
    const int lane = threadIdx.x;
    const int4* __restrict__ t4 = reinterpret_cast<const int4*>(target)
                                  + (long long)blockIdx.x * n_vec4_per_batch;

    unsigned acc = 0u;
    if (lane < n_vec4_per_batch) {
        int4 v = t4[lane];
        acc = (1u << (v.x & 31)) | (1u << (v.y & 31)) |
              (1u << (v.z & 31)) | (1u << (v.w & 31));
    }
    acc = __reduce_or_sync(0xffffffffu, acc) & 0x3Fu;

    if (acc != 0x3Fu) {                        // cold path: finish the scan
        for (int base = 32; base < n_vec4_per_batch; base += 32) {
            int idx = base + lane;
            unsigned a = 0u;
            if (idx < n_vec4_per_batch) {
                int4 v = t4[idx];
                a = (1u << (v.x & 31)) | (1u << (v.y & 31)) |
                    (1u << (v.z & 31)) | (1u << (v.w & 31));
            }
            acc |= __reduce_or_sync(0xffffffffu, a) & 0x3Fu;
            if (acc == 0x3Fu) break;
        }
    }

    if (lane == 0) g_masks[blockIdx.x] = acc;
    __threadfence();                            // mask visible before trigger
    cudaTriggerProgrammaticLaunchCompletion();
}

// ---------------------------------------------------------------------------
// Loss kernel (PDL secondary): 1 block x 384 threads, one (batch,class) term
// each. Prelude (se_pred load + clamped logs) runs CONCURRENTLY with the
// presence kernel; only select+reduce+store follow the dependency sync.
// ---------------------------------------------------------------------------
__global__ void __launch_bounds__(384, 1)
loss_kernel(const float* __restrict__ se_pred,
            float* __restrict__ out, int n_terms) {
    const int i = threadIdx.x;           // 0..383
    float v_present = 0.0f, v_absent = 0.0f;
    int b = 0, c = 0;
    if (i < n_terms) {
        b = i / 6;
        c = i - b * 6;
        const float p = se_pred[i];
        v_present = -fmaxf(logf(p),    -100.0f);   // t = 1 branch
        v_absent  = -fmaxf(log1pf(-p), -100.0f);   // t = 0 branch
    }

    cudaGridDependencySynchronize();     // wait for presence grid's writes

    float v = 0.0f;
    if (i < n_terms) {
        const unsigned m = __ldcg(&g_masks[b]);    // L2 read (cross-kernel)
        v = ((m >> c) & 1u) ? v_present : v_absent;
    }

    // Block reduction: 12 warps -> shared -> warp 0.
    __shared__ float sh[12];
    #pragma unroll
    for (int o = 16; o > 0; o >>= 1) v += __shfl_down_sync(0xffffffffu, v, o);
    if ((i & 31) == 0) sh[i >> 5] = v;
    __syncthreads();
    if (i < 32) {
        float s = (i < 12) ? sh[i] : 0.0f;
        #pragma unroll
        for (int o = 8; o > 0; o >>= 1) s += __shfl_down_sync(0xffffffffu, s, o);
        if (i == 0) out[0] = s / (float)n_terms;
    }
}

// ---------------------------------------------------------------------------
extern "C" void kernel_launch(void* const* d_in, const int* in_sizes, int n_in,
                              void* d_out, int out_size) {
    // Resolve inputs by size: se_pred has 64*6 = 384 elements; target is huge.
    int se_idx = 0, tg_idx = 1;
    if (n_in >= 2 && in_sizes[0] > in_sizes[1]) { se_idx = 1; tg_idx = 0; }

    const float* se_pred = (const float*)d_in[se_idx];
    const int*   target  = (const int*)d_in[tg_idx];
    float* out = (float*)d_out;

    const int n_terms   = in_sizes[se_idx];        // 384
    const int B         = n_terms / 6;             // 64
    const int per_batch = in_sizes[tg_idx] / B;    // 262144 int32 labels
    const int n_vec4    = per_batch / 4;           // int4 count per batch

    presence_kernel<<<B, 32>>>(target, n_vec4);

    // Secondary launch with programmatic stream serialization (PDL): it may
    // begin while presence_kernel runs; cudaGridDependencySynchronize() inside
    // provides the ordering.
    cudaLaunchAttribute attr;
    attr.id = cudaLaunchAttributeProgrammaticStreamSerialization;
    attr.val.programmaticStreamSerializationAllowed = 1;

    cudaLaunchConfig_t cfg = {};
    cfg.gridDim  = dim3(1, 1, 1);
    cfg.blockDim = dim3(384, 1, 1);
    cfg.dynamicSmemBytes = 0;
    cfg.stream = 0;
    cfg.attrs = &attr;
    cfg.numAttrs = 1;

    cudaLaunchKernelEx(&cfg, loss_kernel, se_pred, out, n_terms);
}

// round 9
// speedup vs baseline: 1.1889x; 1.1014x over previous
#include <cuda_runtime.h>
#include <cstdint>

// Per-batch class-presence bitmasks (bits 0..5), B=64. Written by presence
// kernel, read by loss kernel AFTER cudaGridDependencySynchronize() (PDL).
__device__ unsigned g_masks[64];

// ---------------------------------------------------------------------------
// Presence kernel: grid = B blocks x 32 threads (one warp, no smem, no BAR).
// ORs labels (0..5) into a 6-bit mask. First pass covers 128 labels:
// p(miss) ~ 6*(5/6)^128 ~ 4e-10 on uniform data; presence-OR is monotone so
// early exit is exact, adversarial data degrades to a full (correct) scan.
// Triggers programmatic launch completion after publishing its mask.
// ---------------------------------------------------------------------------
__global__ void __launch_bounds__(32, 32)
presence_kernel(const int* __restrict__ target, int n_vec4_per_batch) {
    const int lane = threadIdx.x;
    const int4* __restrict__ t4 = reinterpret_cast<const int4*>(target)
                                  + (long long)blockIdx.x * n_vec4_per_batch;

    unsigned acc = 0u;
    if (lane < n_vec4_per_batch) {
        int4 v = t4[lane];
        acc = (1u << (v.x & 31)) | (1u << (v.y & 31)) |
              (1u << (v.z & 31)) | (1u << (v.w & 31));
    }
    acc = __reduce_or_sync(0xffffffffu, acc) & 0x3Fu;

    if (acc != 0x3Fu) {                        // cold path: finish the scan
        for (int base = 32; base < n_vec4_per_batch; base += 32) {
            int idx = base + lane;
            unsigned a = 0u;
            if (idx < n_vec4_per_batch) {
                int4 v = t4[idx];
                a = (1u << (v.x & 31)) | (1u << (v.y & 31)) |
                    (1u << (v.z & 31)) | (1u << (v.w & 31));
            }
            acc |= __reduce_or_sync(0xffffffffu, a) & 0x3Fu;
            if (acc == 0x3Fu) break;
        }
    }

    if (lane == 0) g_masks[blockIdx.x] = acc;
    __threadfence();                            // mask visible before trigger
    cudaTriggerProgrammaticLaunchCompletion();
}

// ---------------------------------------------------------------------------
// Loss kernel (PDL secondary): 1 block x 384 threads, one (batch,class) term
// each. Prelude (se_pred load + clamped logs) runs CONCURRENTLY with the
// presence kernel; only select+reduce+store follow the dependency sync.
// ---------------------------------------------------------------------------
__global__ void __launch_bounds__(384, 1)
loss_kernel(const float* __restrict__ se_pred,
            float* __restrict__ out, int n_terms) {
    const int i = threadIdx.x;           // 0..383
    float v_present = 0.0f, v_absent = 0.0f;
    int b = 0, c = 0;
    if (i < n_terms) {
        b = i / 6;
        c = i - b * 6;
        const float p = se_pred[i];
        v_present = -fmaxf(logf(p),    -100.0f);   // t = 1 branch
        v_absent  = -fmaxf(log1pf(-p), -100.0f);   // t = 0 branch
    }

    cudaGridDependencySynchronize();     // wait for presence grid's writes

    float v = 0.0f;
    if (i < n_terms) {
        const unsigned m = __ldcg(&g_masks[b]);    // L2 read (cross-kernel)
        v = ((m >> c) & 1u) ? v_present : v_absent;
    }

    // Block reduction: 12 warps -> shared -> warp 0.
    __shared__ float sh[12];
    #pragma unroll
    for (int o = 16; o > 0; o >>= 1) v += __shfl_down_sync(0xffffffffu, v, o);
    if ((i & 31) == 0) sh[i >> 5] = v;
    __syncthreads();
    if (i < 32) {
        float s = (i < 12) ? sh[i] : 0.0f;
        #pragma unroll
        for (int o = 8; o > 0; o >>= 1) s += __shfl_down_sync(0xffffffffu, s, o);
        if (i == 0) out[0] = s / (float)n_terms;
    }
}

// ---------------------------------------------------------------------------
extern "C" void kernel_launch(void* const* d_in, const int* in_sizes, int n_in,
                              void* d_out, int out_size) {
    // Resolve inputs by size: se_pred has 64*6 = 384 elements; target is huge.
    int se_idx = 0, tg_idx = 1;
    if (n_in >= 2 && in_sizes[0] > in_sizes[1]) { se_idx = 1; tg_idx = 0; }

    const float* se_pred = (const float*)d_in[se_idx];
    const int*   target  = (const int*)d_in[tg_idx];
    float* out = (float*)d_out;

    const int n_terms   = in_sizes[se_idx];        // 384
    const int B         = n_terms / 6;             // 64
    const int per_batch = in_sizes[tg_idx] / B;    // 262144 int32 labels
    const int n_vec4    = per_batch / 4;           // int4 count per batch

    presence_kernel<<<B, 32>>>(target, n_vec4);

    // Secondary launch with programmatic stream serialization (PDL): it may
    // begin while presence_kernel runs; cudaGridDependencySynchronize() inside
    // provides the ordering.
    cudaLaunchAttribute attr;
    attr.id = cudaLaunchAttributeProgrammaticStreamSerialization;
    attr.val.programmaticStreamSerializationAllowed = 1;

    cudaLaunchConfig_t cfg = {};
    cfg.gridDim  = dim3(1, 1, 1);
    cfg.blockDim = dim3(384, 1, 1);
    cfg.dynamicSmemBytes = 0;
    cfg.stream = 0;
    cfg.attrs = &attr;
    cfg.numAttrs = 1;

    cudaLaunchKernelEx(&cfg, loss_kernel, se_pred, out, n_terms);
}

// round 10
// speedup vs baseline: 1.3231x; 1.1128x over previous
#include <cuda_runtime.h>
#include <cstdint>

// ---------------------------------------------------------------------------
// Fully batch-local kernel: one warp per batch (grid = B x 32 threads).
// Each warp:
//   1. Prefetches its 6 se_pred values and computes BOTH clamped log terms
//      (torch BCELoss: log clamped at -100) while the target load is in
//      flight (lanes 0..5 only).
//   2. Scans 128 labels of its batch (32 lanes x int4) and OR-reduces a 6-bit
//      presence mask. Presence-OR is monotone, so early exit is exact:
//      p(miss after 128 uniform labels) ~ 6*(5/6)^128 ~ 4e-10; adversarial
//      data degrades to a full (still correct) scan via the cold loop.
//   3. Selects present/absent term per lane, shfl-reduces the 6 terms, and
//      atomicAdds the pre-scaled partial (sum / n_terms) to out[0].
// No inter-block communication, no second compute kernel. out[0] is zeroed
// by a cudaMemsetAsync node in the same graph.
// ---------------------------------------------------------------------------
__global__ void __launch_bounds__(32, 32)
se_loss_batchlocal_kernel(const int* __restrict__ target,
                          const float* __restrict__ se_pred,
                          float* __restrict__ out,
                          int n_vec4_per_batch, int n_terms) {
    const int lane = threadIdx.x;
    const int b    = blockIdx.x;

    // --- issue the target load first (longest latency) ---
    const int4* __restrict__ t4 = reinterpret_cast<const int4*>(target)
                                  + (long long)b * n_vec4_per_batch;
    int4 v0 = make_int4(0, 0, 0, 0);
    const bool ld0 = (lane < n_vec4_per_batch);
    if (ld0) v0 = t4[lane];

    // --- overlap: BCE log terms for this batch (lanes 0..5) ---
    const int term_idx = b * 6 + lane;
    const bool term_valid = (lane < 6) && (term_idx < n_terms);
    float v_present = 0.0f, v_absent = 0.0f;
    if (term_valid) {
        const float p = se_pred[term_idx];
        v_present = -fmaxf(logf(p),    -100.0f);   // t = 1
        v_absent  = -fmaxf(log1pf(-p), -100.0f);   // t = 0
    }

    // --- presence mask ---
    unsigned acc = 0u;
    if (ld0) {
        acc = (1u << (v0.x & 31)) | (1u << (v0.y & 31)) |
              (1u << (v0.z & 31)) | (1u << (v0.w & 31));
    }
    acc = __reduce_or_sync(0xffffffffu, acc) & 0x3Fu;

    if (acc != 0x3Fu) {                          // cold path: finish the scan
        for (int base = 32; base < n_vec4_per_batch; base += 32) {
            int idx = base + lane;
            unsigned a = 0u;
            if (idx < n_vec4_per_batch) {
                int4 v = t4[idx];
                a = (1u << (v.x & 31)) | (1u << (v.y & 31)) |
                    (1u << (v.z & 31)) | (1u << (v.w & 31));
            }
            acc |= __reduce_or_sync(0xffffffffu, a) & 0x3Fu;
            if (acc == 0x3Fu) break;
        }
    }

    // --- select + reduce 6 terms, accumulate ---
    float v = 0.0f;
    if (term_valid)
        v = ((acc >> lane) & 1u) ? v_present : v_absent;
    #pragma unroll
    for (int o = 4; o > 0; o >>= 1) v += __shfl_down_sync(0xffffffffu, v, o);
    // lanes 0 and 4..5 handled: offsets 4,2,1 cover lanes 0..7 fully from 0..5? No:
    // offsets {4,2,1} sum lanes 0..7 into lane 0; lanes 6,7 carry v=0. Correct.
    if (lane == 0) atomicAdd(out, v / (float)n_terms);
}

// ---------------------------------------------------------------------------
extern "C" void kernel_launch(void* const* d_in, const int* in_sizes, int n_in,
                              void* d_out, int out_size) {
    // Resolve inputs by size: se_pred has 64*6 = 384 elements; target is huge.
    int se_idx = 0, tg_idx = 1;
    if (n_in >= 2 && in_sizes[0] > in_sizes[1]) { se_idx = 1; tg_idx = 0; }

    const float* se_pred = (const float*)d_in[se_idx];
    const int*   target  = (const int*)d_in[tg_idx];
    float* out = (float*)d_out;

    const int n_terms   = in_sizes[se_idx];        // 384
    const int B         = n_terms / 6;             // 64
    const int per_batch = in_sizes[tg_idx] / B;    // 262144 int32 labels
    const int n_vec4    = per_batch / 4;           // int4 count per batch

    cudaMemsetAsync(out, 0, sizeof(float), 0);     // zero the accumulator
    se_loss_batchlocal_kernel<<<B, 32>>>(target, se_pred, out, n_vec4, n_terms);
}